// round 1
// baseline (speedup 1.0000x reference)
#include <cuda_runtime.h>

#define TT   4
#define NN   20000
#define EE   640000
#define DIN  256
#define DOUT 128
#define SLOPE 0.22916666666666666f

// ---------------- scratch (__device__ globals; no allocation) ----------------
__device__ float g_scores[NN];
__device__ int   g_idx[DOUT];
__device__ float g_tanhvals[DOUT];
__device__ float g_xt[DIN * DOUT];          // [256][128] row-major
__device__ float g_Wbuf[2][DIN * DOUT];     // evolving GRU hidden (the GCN weight)
__device__ float g_WT[6 * DIN * DIN];       // transposed Wz,Uz,Wr,Ur,Wh,Uh
__device__ float g_y[NN * DOUT];            // x @ Wn
__device__ int   g_deg[NN];
__device__ int   g_off[NN + 1];
__device__ int   g_cur[NN];
__device__ int   g_csr_src[EE];
__device__ float g_csr_w[EE];
__device__ float g_invnorm;

// ---------------- helpers ----------------
__device__ __forceinline__ unsigned ord_of(float f) {
    unsigned b = __float_as_uint(f);
    return b ^ ((b & 0x80000000u) ? 0xFFFFFFFFu : 0x80000000u);
}
__device__ __forceinline__ float sigmoidf_(float x) {
    return 1.0f / (1.0f + expf(-x));
}

// ---------------- prep: invnorm, transpose 6 weight mats, copy W0 ----------------
__global__ void prep_kernel(const float* __restrict__ p,
                            const float* __restrict__ Wz, const float* __restrict__ Uz,
                            const float* __restrict__ Wr, const float* __restrict__ Ur,
                            const float* __restrict__ Wh, const float* __restrict__ Uh,
                            const float* __restrict__ W0) {
    if (blockIdx.x == 0) {
        __shared__ float red[256];
        float v = p[threadIdx.x];
        red[threadIdx.x] = v * v;
        __syncthreads();
        for (int s = 128; s > 0; s >>= 1) {
            if (threadIdx.x < s) red[threadIdx.x] += red[threadIdx.x + s];
            __syncthreads();
        }
        if (threadIdx.x == 0) g_invnorm = rsqrtf(red[0]);
    }
    const float* srcs[6] = {Wz, Uz, Wr, Ur, Wh, Uh};
    const int total = 6 * DIN * DIN + DIN * DOUT;
    for (int idx = blockIdx.x * blockDim.x + threadIdx.x; idx < total;
         idx += gridDim.x * blockDim.x) {
        if (idx < 6 * DIN * DIN) {
            int m = idx >> 16;          // which matrix
            int e = idx & 0xFFFF;       // output linear index: e = k*256 + i
            int k = e >> 8, i = e & 255;
            g_WT[idx] = srcs[m][i * DIN + k];
        } else {
            int e = idx - 6 * DIN * DIN;
            g_Wbuf[0][e] = W0[e];
        }
    }
}

// ---------------- scores: (x @ p)/||p|| + mask ----------------
__global__ void scores_kernel(const float* __restrict__ x,
                              const float* __restrict__ p,
                              const float* __restrict__ mask) {
    __shared__ float sp[DIN];
    int tid = threadIdx.x;
    sp[tid] = p[tid];
    __syncthreads();
    int warp = tid >> 5, lane = tid & 31;
    int n = blockIdx.x * 8 + warp;
    if (n >= NN) return;
    const float* xr = x + (long)n * DIN;
    float s = 0.0f;
#pragma unroll
    for (int i = 0; i < 8; i++) s += xr[lane + i * 32] * sp[lane + i * 32];
#pragma unroll
    for (int o = 16; o > 0; o >>= 1) s += __shfl_down_sync(0xFFFFFFFFu, s, o);
    if (lane == 0) g_scores[n] = s * g_invnorm + mask[n];
}

// ---------------- top-128 (radix-select + exact ranking) ----------------
__global__ void topk_kernel() {
    __shared__ unsigned hist[256];
    __shared__ unsigned s_prefix;
    __shared__ int s_kneed;
    __shared__ unsigned cnt_gt, cnt_eq;
    __shared__ int eq_idx[256];
    __shared__ unsigned sel_ord[DOUT];
    __shared__ int sel_idx[DOUT];

    int tid = threadIdx.x;                 // 1024 threads
    unsigned prefix = 0;
    int kneed = DOUT;

    for (int shift = 24; shift >= 0; shift -= 8) {
        if (tid < 256) hist[tid] = 0;
        __syncthreads();
        for (int n = tid; n < NN; n += 1024) {
            unsigned ord = ord_of(g_scores[n]);
            bool match = (shift == 24) || ((ord >> (shift + 8)) == prefix);
            if (match) atomicAdd(&hist[(ord >> shift) & 255], 1u);
        }
        __syncthreads();
        if (tid == 0) {
            int cum = 0, b = 255;
            for (; b >= 0; b--) {
                if (cum + (int)hist[b] >= kneed) break;
                cum += (int)hist[b];
            }
            if (b < 0) b = 0;  // safety
            s_prefix = (prefix << 8) | (unsigned)b;
            s_kneed = kneed - cum;
        }
        __syncthreads();
        prefix = s_prefix;
        kneed = s_kneed;
        __syncthreads();
    }
    unsigned T = prefix;

    if (tid == 0) { cnt_gt = 0; cnt_eq = 0; }
    __syncthreads();
    for (int n = tid; n < NN; n += 1024) {
        unsigned ord = ord_of(g_scores[n]);
        if (ord > T) {
            unsigned pos = atomicAdd(&cnt_gt, 1u);
            if (pos < DOUT) { sel_ord[pos] = ord; sel_idx[pos] = n; }
        } else if (ord == T) {
            unsigned pos = atomicAdd(&cnt_eq, 1u);
            if (pos < 256) eq_idx[pos] = n;
        }
    }
    __syncthreads();
    int ngt = (int)cnt_gt;
    int ne = (int)cnt_eq; if (ne > 256) ne = 256;
    if (tid < ne) {
        int my = eq_idx[tid];
        int r = 0;
        for (int i = 0; i < ne; i++) r += (eq_idx[i] < my);
        if (r < kneed && ngt + r < DOUT) { sel_ord[ngt + r] = T; sel_idx[ngt + r] = my; }
    }
    __syncthreads();
    if (tid < DOUT) {
        unsigned myo = sel_ord[tid];
        int myi = sel_idx[tid];
        int r = 0;
#pragma unroll 4
        for (int i = 0; i < DOUT; i++) {
            unsigned o = sel_ord[i];
            r += (o > myo) || (o == myo && sel_idx[i] < myi);
        }
        g_idx[r] = myi;
        g_tanhvals[r] = tanhf(g_scores[myi]);
    }
}

// ---------------- build xt: xt[d][j] = x[idx[j]][d] * tanh(val[j]) ----------------
__global__ void xt_kernel(const float* __restrict__ x) {
    int j = blockIdx.x;      // 128 blocks
    int d = threadIdx.x;     // 256 threads
    float tv = g_tanhvals[j];
    int n = g_idx[j];
    g_xt[d * DOUT + j] = x[(long)n * DIN + d] * tv;
}

// ---------------- fused matrix-GRU: z, r, h, Wn (4 cols per block) ----------------
#define GCOLS 4
__global__ void gru_kernel(const float* __restrict__ Wcur, float* __restrict__ Wnext,
                           const float* __restrict__ bz, const float* __restrict__ br,
                           const float* __restrict__ bh) {
    __shared__ __align__(16) float xts[DIN * GCOLS];
    __shared__ __align__(16) float Ws[DIN * GCOLS];
    __shared__ __align__(16) float rws[DIN * GCOLS];
    int i = threadIdx.x;            // row 0..255
    int j0 = blockIdx.x * GCOLS;    // 32 blocks
#pragma unroll
    for (int c = 0; c < GCOLS; c++) {
        xts[i * GCOLS + c] = g_xt[i * DOUT + j0 + c];
        Ws[i * GCOLS + c]  = Wcur[i * DOUT + j0 + c];
    }
    __syncthreads();

    const float* WzT = g_WT + 0 * DIN * DIN;
    const float* UzT = g_WT + 1 * DIN * DIN;
    const float* WrT = g_WT + 2 * DIN * DIN;
    const float* UrT = g_WT + 3 * DIN * DIN;
    const float* WhT = g_WT + 4 * DIN * DIN;
    const float* UhT = g_WT + 5 * DIN * DIN;

    float az[GCOLS] = {0, 0, 0, 0}, ar[GCOLS] = {0, 0, 0, 0};
#pragma unroll 4
    for (int k = 0; k < DIN; k++) {
        float wz = WzT[k * DIN + i], uz = UzT[k * DIN + i];
        float wr = WrT[k * DIN + i], ur = UrT[k * DIN + i];
        float4 xv = *(const float4*)&xts[k * GCOLS];
        float4 wv = *(const float4*)&Ws[k * GCOLS];
        az[0] += wz * xv.x + uz * wv.x;  ar[0] += wr * xv.x + ur * wv.x;
        az[1] += wz * xv.y + uz * wv.y;  ar[1] += wr * xv.y + ur * wv.y;
        az[2] += wz * xv.z + uz * wv.z;  ar[2] += wr * xv.z + ur * wv.z;
        az[3] += wz * xv.w + uz * wv.w;  ar[3] += wr * xv.w + ur * wv.w;
    }
    float z[GCOLS], r[GCOLS];
#pragma unroll
    for (int c = 0; c < GCOLS; c++) {
        z[c] = sigmoidf_(az[c] + bz[i * DOUT + j0 + c]);
        r[c] = sigmoidf_(ar[c] + br[i * DOUT + j0 + c]);
        rws[i * GCOLS + c] = r[c] * Ws[i * GCOLS + c];
    }
    __syncthreads();

    float ah[GCOLS] = {0, 0, 0, 0};
#pragma unroll 4
    for (int k = 0; k < DIN; k++) {
        float wh = WhT[k * DIN + i], uh = UhT[k * DIN + i];
        float4 xv = *(const float4*)&xts[k * GCOLS];
        float4 rv = *(const float4*)&rws[k * GCOLS];
        ah[0] += wh * xv.x + uh * rv.x;
        ah[1] += wh * xv.y + uh * rv.y;
        ah[2] += wh * xv.z + uh * rv.z;
        ah[3] += wh * xv.w + uh * rv.w;
    }
#pragma unroll
    for (int c = 0; c < GCOLS; c++) {
        float h = tanhf(ah[c] + bh[i * DOUT + j0 + c]);
        float Wv = Ws[i * GCOLS + c];
        Wnext[i * DOUT + j0 + c] = (1.0f - z[c]) * Wv + z[c] * h;
    }
}

// ---------------- SGEMM: y[20000,128] = x[20000,256] @ Wn[256,128] ----------------
#define BM 64
#define BN 128
#define BK 16
__global__ void sgemm_kernel(const float* __restrict__ A, const float* __restrict__ B,
                             float* __restrict__ C) {
    __shared__ __align__(16) float As[BK][BM + 1];
    __shared__ __align__(16) float Bs[BK][BN];
    int tid = threadIdx.x;           // 256
    int bm = blockIdx.x * BM;
    int tx = tid & 31;               // col quad: cols tx*4..tx*4+3
    int ty = tid >> 5;               // row group: rows ty*8..ty*8+7
    int rowA = tid >> 2, qA = tid & 3;

    float acc[8][4];
#pragma unroll
    for (int m = 0; m < 8; m++)
#pragma unroll
        for (int c = 0; c < 4; c++) acc[m][c] = 0.0f;

    for (int k0 = 0; k0 < DIN; k0 += BK) {
        {
            int gr = bm + rowA;
            float4 a4 = make_float4(0.f, 0.f, 0.f, 0.f);
            if (gr < NN) a4 = *(const float4*)&A[(long)gr * DIN + k0 + qA * 4];
            As[qA * 4 + 0][rowA] = a4.x;
            As[qA * 4 + 1][rowA] = a4.y;
            As[qA * 4 + 2][rowA] = a4.z;
            As[qA * 4 + 3][rowA] = a4.w;
        }
#pragma unroll
        for (int l = 0; l < 2; l++) {
            int q = tid + l * 256;       // 512 float4 slots
            int kk = q >> 5;
            int c4 = q & 31;
            *(float4*)&Bs[kk][c4 * 4] = *(const float4*)&B[(k0 + kk) * BN + c4 * 4];
        }
        __syncthreads();
#pragma unroll
        for (int kk = 0; kk < BK; kk++) {
            float a[8];
#pragma unroll
            for (int m = 0; m < 8; m++) a[m] = As[kk][ty * 8 + m];
            float4 b = *(const float4*)&Bs[kk][tx * 4];
#pragma unroll
            for (int m = 0; m < 8; m++) {
                acc[m][0] += a[m] * b.x;
                acc[m][1] += a[m] * b.y;
                acc[m][2] += a[m] * b.z;
                acc[m][3] += a[m] * b.w;
            }
        }
        __syncthreads();
    }
#pragma unroll
    for (int m = 0; m < 8; m++) {
        int gr = bm + ty * 8 + m;
        if (gr < NN)
            *(float4*)&C[(long)gr * BN + tx * 4] =
                make_float4(acc[m][0], acc[m][1], acc[m][2], acc[m][3]);
    }
}

// ---------------- CSR build ----------------
__global__ void zero_deg_kernel() {
    int n = blockIdx.x * blockDim.x + threadIdx.x;
    if (n < NN) g_deg[n] = 0;
}
__global__ void deg_kernel(const int* __restrict__ dst) {
    int e = blockIdx.x * blockDim.x + threadIdx.x;
    if (e < EE) atomicAdd(&g_deg[dst[e]], 1);
}
__global__ void scan_kernel() {
    __shared__ int part[1024];
    int tid = threadIdx.x;
    int base = tid * 20;
    int loc[20];
    int sum = 0;
#pragma unroll
    for (int i = 0; i < 20; i++) {
        int n = base + i;
        int d = (n < NN) ? g_deg[n] : 0;
        loc[i] = sum;
        sum += d;
    }
    part[tid] = sum;
    __syncthreads();
    for (int off = 1; off < 1024; off <<= 1) {
        int v = (tid >= off) ? part[tid - off] : 0;
        __syncthreads();
        part[tid] += v;
        __syncthreads();
    }
    int myoff = tid ? part[tid - 1] : 0;
#pragma unroll
    for (int i = 0; i < 20; i++) {
        int n = base + i;
        if (n <= NN) {
            int o = myoff + loc[i];
            g_off[n] = o;
            if (n < NN) g_cur[n] = o;
        }
    }
}
__global__ void fill_kernel(const int* __restrict__ dst, const int* __restrict__ src,
                            const float* __restrict__ w) {
    int e = blockIdx.x * blockDim.x + threadIdx.x;
    if (e >= EE) return;
    int d = dst[e];
    int pos = atomicAdd(&g_cur[d], 1);
    g_csr_src[pos] = src[e];
    g_csr_w[pos] = w[e];
}

// ---------------- gather + RReLU: out[n] = rrelu(sum_e w_e * y[src_e]) ----------------
__global__ void gather_kernel(float* __restrict__ out) {
    int node = blockIdx.x * (blockDim.x >> 5) + (threadIdx.x >> 5);
    if (node >= NN) return;
    int lane = threadIdx.x & 31;
    int beg = g_off[node], end = g_off[node + 1];
    float4 acc = make_float4(0.f, 0.f, 0.f, 0.f);
    int e = beg;
    // unroll-2 for MLP
    for (; e + 1 < end; e += 2) {
        int s0 = g_csr_src[e];     float w0 = g_csr_w[e];
        int s1 = g_csr_src[e + 1]; float w1 = g_csr_w[e + 1];
        float4 v0 = *(const float4*)&g_y[(long)s0 * DOUT + lane * 4];
        float4 v1 = *(const float4*)&g_y[(long)s1 * DOUT + lane * 4];
        acc.x += w0 * v0.x + w1 * v1.x;
        acc.y += w0 * v0.y + w1 * v1.y;
        acc.z += w0 * v0.z + w1 * v1.z;
        acc.w += w0 * v0.w + w1 * v1.w;
    }
    if (e < end) {
        int s0 = g_csr_src[e]; float w0 = g_csr_w[e];
        float4 v0 = *(const float4*)&g_y[(long)s0 * DOUT + lane * 4];
        acc.x += w0 * v0.x; acc.y += w0 * v0.y; acc.z += w0 * v0.z; acc.w += w0 * v0.w;
    }
    acc.x = (acc.x >= 0.f) ? acc.x : SLOPE * acc.x;
    acc.y = (acc.y >= 0.f) ? acc.y : SLOPE * acc.y;
    acc.z = (acc.z >= 0.f) ? acc.z : SLOPE * acc.z;
    acc.w = (acc.w >= 0.f) ? acc.w : SLOPE * acc.w;
    *(float4*)&out[(long)node * DOUT + lane * 4] = acc;
}

// ---------------- launcher ----------------
extern "C" void kernel_launch(void* const* d_in, const int* in_sizes, int n_in,
                              void* d_out, int out_size) {
    const float* node_embs  = (const float*)d_in[0];   // [T,N,256]
    const int*   edge_index = (const int*)d_in[1];     // [T,2,E]
    const float* edge_w     = (const float*)d_in[2];   // [T,E]
    const float* mask       = (const float*)d_in[3];   // [T,N]
    const float* p          = (const float*)d_in[4];   // [256,1]
    const float* Wz         = (const float*)d_in[5];
    const float* Uz         = (const float*)d_in[6];
    const float* bz         = (const float*)d_in[7];
    const float* Wr         = (const float*)d_in[8];
    const float* Ur         = (const float*)d_in[9];
    const float* br         = (const float*)d_in[10];
    const float* Wh         = (const float*)d_in[11];
    const float* Uh         = (const float*)d_in[12];
    const float* bh         = (const float*)d_in[13];
    const float* W0         = (const float*)d_in[14];
    float* out = (float*)d_out;                        // [T,N,128]

    prep_kernel<<<256, 256>>>(p, Wz, Uz, Wr, Ur, Wh, Uh, W0);

    float* Wa;  float* Wb;
    // resolve device symbol addresses via kernels' direct use; host just toggles index
    for (int t = 0; t < TT; t++) {
        const float* xt_ = node_embs + (long)t * NN * DIN;
        const int* dst   = edge_index + (long)t * 2 * EE;
        const int* src   = dst + EE;
        const float* w   = edge_w + (long)t * EE;
        const float* mk  = mask + (long)t * NN;
        float* out_t     = out + (long)t * NN * DOUT;
        int cur = t & 1, nxt = cur ^ 1;

        zero_deg_kernel<<<(NN + 255) / 256, 256>>>();
        deg_kernel<<<EE / 256, 256>>>(dst);
        scan_kernel<<<1, 1024>>>();
        fill_kernel<<<EE / 256, 256>>>(dst, src, w);

        scores_kernel<<<(NN + 7) / 8, 256>>>(xt_, p, mk);
        topk_kernel<<<1, 1024>>>();
        xt_kernel<<<DOUT, DIN>>>(xt_);

        // device-symbol pointers: take address through a tiny trick — use
        // cudaGetSymbolAddress is host API (allowed, not allocation) but we can
        // avoid it entirely by passing buffer index through kernel args.
        // Simplest: two static device pointers resolved once per launch:
        {
            static float* wptr0 = nullptr;
            static float* wptr1 = nullptr;
            if (!wptr0) {
                void* a; cudaGetSymbolAddress(&a, g_Wbuf);
                wptr0 = (float*)a;
                wptr1 = wptr0 + DIN * DOUT;
            }
            Wa = (cur == 0) ? wptr0 : wptr1;
            Wb = (cur == 0) ? wptr1 : wptr0;
        }
        gru_kernel<<<DOUT / GCOLS, DIN>>>(Wa, Wb, bz, br, bh);

        {
            static float* yptr = nullptr;
            if (!yptr) { void* a; cudaGetSymbolAddress(&a, g_y); yptr = (float*)a; }
            sgemm_kernel<<<(NN + BM - 1) / BM, 256>>>(xt_, Wb, yptr);
        }

        gather_kernel<<<(NN + 7) / 8, 256>>>(out_t);
    }
}

// round 2
// speedup vs baseline: 1.6844x; 1.6844x over previous
#include <cuda_runtime.h>

#define TT   4
#define NN   20000
#define EE   640000
#define DIN  256
#define DOUT 128
#define SLOPE 0.22916666666666666f

typedef unsigned long long ull;

// ---------------- scratch (__device__ globals; no allocation) ----------------
__device__ float g_scores[TT * NN];
__device__ int   g_idx[TT * DOUT];
__device__ float g_tanhvals[TT * DOUT];
__device__ float g_xt[TT * DIN * DOUT];          // per-t [256][128]
__device__ float g_Wn[(TT + 1) * DIN * DOUT];    // W0 + evolved weights
__device__ float g_WT[6 * DIN * DIN];            // transposed Wz,Uz,Wr,Ur,Wh,Uh
__device__ float g_y[(size_t)TT * NN * DOUT];    // x_t @ Wn_t  (41 MB)
__device__ int   g_deg[TT * NN];
__device__ int   g_off[TT * (NN + 1)];
__device__ int   g_cur[TT * NN];
__device__ int   g_csr_src[(size_t)TT * EE];
__device__ float g_csr_w[(size_t)TT * EE];
__device__ float g_invnorm;

// ---------------- helpers ----------------
__device__ __forceinline__ unsigned ord_of(float f) {
    unsigned b = __float_as_uint(f);
    return b ^ ((b & 0x80000000u) ? 0xFFFFFFFFu : 0x80000000u);
}
__device__ __forceinline__ float sigmoidf_(float x) {
    return 1.0f / (1.0f + expf(-x));
}

// ---------------- prep: invnorm, transpose 6 weight mats, copy W0 ----------------
__global__ void prep_kernel(const float* __restrict__ p,
                            const float* __restrict__ Wz, const float* __restrict__ Uz,
                            const float* __restrict__ Wr, const float* __restrict__ Ur,
                            const float* __restrict__ Wh, const float* __restrict__ Uh,
                            const float* __restrict__ W0) {
    if (blockIdx.x == 0) {
        __shared__ float red[256];
        float v = p[threadIdx.x];
        red[threadIdx.x] = v * v;
        __syncthreads();
        for (int s = 128; s > 0; s >>= 1) {
            if (threadIdx.x < s) red[threadIdx.x] += red[threadIdx.x + s];
            __syncthreads();
        }
        if (threadIdx.x == 0) g_invnorm = rsqrtf(red[0]);
    }
    const float* srcs[6] = {Wz, Uz, Wr, Ur, Wh, Uh};
    const int total = 6 * DIN * DIN + DIN * DOUT;
    for (int idx = blockIdx.x * blockDim.x + threadIdx.x; idx < total;
         idx += gridDim.x * blockDim.x) {
        if (idx < 6 * DIN * DIN) {
            int m = idx >> 16;          // which matrix
            int e = idx & 0xFFFF;       // output linear index: e = k*256 + i
            int k = e >> 8, i = e & 255;
            g_WT[idx] = srcs[m][i * DIN + k];
        } else {
            int e = idx - 6 * DIN * DIN;
            g_Wn[e] = W0[e];
        }
    }
}

// ---------------- CSR build (batched over t) ----------------
__global__ void zero_deg_all_kernel() {
    int n = blockIdx.x * blockDim.x + threadIdx.x;
    if (n < TT * NN) g_deg[n] = 0;
}
__global__ void deg_all_kernel(const int* __restrict__ ei) {
    int t = blockIdx.y;
    int e = blockIdx.x * blockDim.x + threadIdx.x;
    const int* dst = ei + (size_t)t * 2 * EE;
    atomicAdd(&g_deg[t * NN + dst[e]], 1);
}
__global__ void fill_all_kernel(const int* __restrict__ ei, const float* __restrict__ w) {
    int t = blockIdx.y;
    int e = blockIdx.x * blockDim.x + threadIdx.x;
    const int* dst = ei + (size_t)t * 2 * EE;
    const int* src = dst + EE;
    int d = dst[e];
    int pos = atomicAdd(&g_cur[t * NN + d], 1);
    g_csr_src[(size_t)t * EE + pos] = src[e];
    g_csr_w[(size_t)t * EE + pos] = w[(size_t)t * EE + e];
}

// ---------------- scores: (x @ p)/||p|| + mask (batched) ----------------
__global__ void scores_all_kernel(const float* __restrict__ embs,
                                  const float* __restrict__ p,
                                  const float* __restrict__ mask) {
    __shared__ float sp[DIN];
    int tid = threadIdx.x;
    sp[tid] = p[tid];
    __syncthreads();
    int t = blockIdx.y;
    int warp = tid >> 5, lane = tid & 31;
    int n = blockIdx.x * 8 + warp;
    if (n >= NN) return;
    const float* xr = embs + ((size_t)t * NN + n) * DIN;
    float4 x0 = *(const float4*)&xr[lane * 4];
    float4 x1 = *(const float4*)&xr[128 + lane * 4];
    float4 p0 = *(const float4*)&sp[lane * 4];
    float4 p1 = *(const float4*)&sp[128 + lane * 4];
    float s = x0.x * p0.x + x0.y * p0.y + x0.z * p0.z + x0.w * p0.w
            + x1.x * p1.x + x1.y * p1.y + x1.z * p1.z + x1.w * p1.w;
#pragma unroll
    for (int o = 16; o > 0; o >>= 1) s += __shfl_down_sync(0xFFFFFFFFu, s, o);
    if (lane == 0) g_scores[t * NN + n] = s * g_invnorm + mask[t * NN + n];
}

// ---------------- scan (per-t CSR offsets) ----------------
__device__ void do_scan(int t) {
    __shared__ int part[1024];
    int tid = threadIdx.x;
    const int* deg = g_deg + t * NN;
    int* off = g_off + t * (NN + 1);
    int* cur = g_cur + t * NN;
    int base = tid * 20;
    int loc[20];
    int sum = 0;
#pragma unroll
    for (int i = 0; i < 20; i++) {
        int n = base + i;
        int d = (n < NN) ? deg[n] : 0;
        loc[i] = sum;
        sum += d;
    }
    part[tid] = sum;
    __syncthreads();
    for (int o = 1; o < 1024; o <<= 1) {
        int v = (tid >= o) ? part[tid - o] : 0;
        __syncthreads();
        part[tid] += v;
        __syncthreads();
    }
    int myoff = tid ? part[tid - 1] : 0;
#pragma unroll
    for (int i = 0; i < 20; i++) {
        int n = base + i;
        if (n <= NN) {
            int o = myoff + loc[i];
            off[n] = o;
            if (n < NN) cur[n] = o;
        }
    }
}

// ---------------- top-128 + xt build (per-t) ----------------
__device__ void do_topk(int t, const float* __restrict__ embs) {
    __shared__ unsigned hist[256];
    __shared__ unsigned s_prefix;
    __shared__ int s_kneed;
    __shared__ unsigned cnt_gt, cnt_eq;
    __shared__ int eq_idx[256];
    __shared__ unsigned sel_ord[DOUT];
    __shared__ int sel_idx[DOUT];
    __shared__ int sh_idx[DOUT];
    __shared__ float sh_tanh[DOUT];

    const float* scores = g_scores + t * NN;
    int tid = threadIdx.x;                 // 1024 threads
    unsigned prefix = 0;
    int kneed = DOUT;

    for (int shift = 24; shift >= 0; shift -= 8) {
        if (tid < 256) hist[tid] = 0;
        __syncthreads();
        for (int n = tid; n < NN; n += 1024) {
            unsigned ord = ord_of(scores[n]);
            bool match = (shift == 24) || ((ord >> (shift + 8)) == prefix);
            if (match) atomicAdd(&hist[(ord >> shift) & 255], 1u);
        }
        __syncthreads();
        if (tid == 0) {
            int cum = 0, b = 255;
            for (; b >= 0; b--) {
                if (cum + (int)hist[b] >= kneed) break;
                cum += (int)hist[b];
            }
            if (b < 0) b = 0;  // safety
            s_prefix = (prefix << 8) | (unsigned)b;
            s_kneed = kneed - cum;
        }
        __syncthreads();
        prefix = s_prefix;
        kneed = s_kneed;
        __syncthreads();
    }
    unsigned T = prefix;

    if (tid == 0) { cnt_gt = 0; cnt_eq = 0; }
    __syncthreads();
    for (int n = tid; n < NN; n += 1024) {
        unsigned ord = ord_of(scores[n]);
        if (ord > T) {
            unsigned pos = atomicAdd(&cnt_gt, 1u);
            if (pos < DOUT) { sel_ord[pos] = ord; sel_idx[pos] = n; }
        } else if (ord == T) {
            unsigned pos = atomicAdd(&cnt_eq, 1u);
            if (pos < 256) eq_idx[pos] = n;
        }
    }
    __syncthreads();
    int ngt = (int)cnt_gt;
    int ne = (int)cnt_eq; if (ne > 256) ne = 256;
    if (tid < ne) {
        int my = eq_idx[tid];
        int r = 0;
        for (int i = 0; i < ne; i++) r += (eq_idx[i] < my);
        if (r < kneed && ngt + r < DOUT) { sel_ord[ngt + r] = T; sel_idx[ngt + r] = my; }
    }
    __syncthreads();
    if (tid < DOUT) {
        unsigned myo = sel_ord[tid];
        int myi = sel_idx[tid];
        int r = 0;
#pragma unroll 4
        for (int i = 0; i < DOUT; i++) {
            unsigned o = sel_ord[i];
            r += (o > myo) || (o == myo && sel_idx[i] < myi);
        }
        g_idx[t * DOUT + r] = myi;
        float tv = tanhf(scores[myi]);
        g_tanhvals[t * DOUT + r] = tv;
        sh_idx[r] = myi;
        sh_tanh[r] = tv;
    }
    __syncthreads();
    // build xt: xt[d][j] = x[idx[j]][d] * tanh(val[j]); e = j*DIN + d (coalesced reads)
    float* xt = g_xt + t * DIN * DOUT;
    for (int e = tid; e < DIN * DOUT; e += 1024) {
        int j = e >> 8;       // e / DIN
        int d = e & 255;      // e % DIN
        xt[d * DOUT + j] = embs[((size_t)t * NN + sh_idx[j]) * DIN + d] * sh_tanh[j];
    }
}

// blocks 0..3: scan(t);  blocks 4..7: topk+xt(t)
__global__ void mid_kernel(const float* __restrict__ embs) {
    if (blockIdx.x < TT) do_scan(blockIdx.x);
    else                 do_topk(blockIdx.x - TT, embs);
}

// ---------------- fused matrix-GRU: z, r, h, Wn (4 cols per block) ----------------
#define GCOLS 4
__global__ void gru_kernel(int t,
                           const float* __restrict__ bz, const float* __restrict__ br,
                           const float* __restrict__ bh) {
    __shared__ __align__(16) float xts[DIN * GCOLS];
    __shared__ __align__(16) float Ws[DIN * GCOLS];
    __shared__ __align__(16) float rws[DIN * GCOLS];
    const float* xt   = g_xt + t * DIN * DOUT;
    const float* Wcur = g_Wn + t * DIN * DOUT;
    float* Wnext      = g_Wn + (t + 1) * DIN * DOUT;
    int i = threadIdx.x;            // row 0..255
    int j0 = blockIdx.x * GCOLS;    // 32 blocks
#pragma unroll
    for (int c = 0; c < GCOLS; c++) {
        xts[i * GCOLS + c] = xt[i * DOUT + j0 + c];
        Ws[i * GCOLS + c]  = Wcur[i * DOUT + j0 + c];
    }
    __syncthreads();

    const float* WzT = g_WT + 0 * DIN * DIN;
    const float* UzT = g_WT + 1 * DIN * DIN;
    const float* WrT = g_WT + 2 * DIN * DIN;
    const float* UrT = g_WT + 3 * DIN * DIN;
    const float* WhT = g_WT + 4 * DIN * DIN;
    const float* UhT = g_WT + 5 * DIN * DIN;

    float az[GCOLS] = {0, 0, 0, 0}, ar[GCOLS] = {0, 0, 0, 0};
#pragma unroll 4
    for (int k = 0; k < DIN; k++) {
        float wz = WzT[k * DIN + i], uz = UzT[k * DIN + i];
        float wr = WrT[k * DIN + i], ur = UrT[k * DIN + i];
        float4 xv = *(const float4*)&xts[k * GCOLS];
        float4 wv = *(const float4*)&Ws[k * GCOLS];
        az[0] += wz * xv.x + uz * wv.x;  ar[0] += wr * xv.x + ur * wv.x;
        az[1] += wz * xv.y + uz * wv.y;  ar[1] += wr * xv.y + ur * wv.y;
        az[2] += wz * xv.z + uz * wv.z;  ar[2] += wr * xv.z + ur * wv.z;
        az[3] += wz * xv.w + uz * wv.w;  ar[3] += wr * xv.w + ur * wv.w;
    }
    float z[GCOLS], r[GCOLS];
#pragma unroll
    for (int c = 0; c < GCOLS; c++) {
        z[c] = sigmoidf_(az[c] + bz[i * DOUT + j0 + c]);
        r[c] = sigmoidf_(ar[c] + br[i * DOUT + j0 + c]);
        rws[i * GCOLS + c] = r[c] * Ws[i * GCOLS + c];
    }
    __syncthreads();

    float ah[GCOLS] = {0, 0, 0, 0};
#pragma unroll 4
    for (int k = 0; k < DIN; k++) {
        float wh = WhT[k * DIN + i], uh = UhT[k * DIN + i];
        float4 xv = *(const float4*)&xts[k * GCOLS];
        float4 rv = *(const float4*)&rws[k * GCOLS];
        ah[0] += wh * xv.x + uh * rv.x;
        ah[1] += wh * xv.y + uh * rv.y;
        ah[2] += wh * xv.z + uh * rv.z;
        ah[3] += wh * xv.w + uh * rv.w;
    }
#pragma unroll
    for (int c = 0; c < GCOLS; c++) {
        float h = tanhf(ah[c] + bh[i * DOUT + j0 + c]);
        float Wv = Ws[i * GCOLS + c];
        Wnext[i * DOUT + j0 + c] = (1.0f - z[c]) * Wv + z[c] * h;
    }
}

// ---------------- SGEMM (batched, packed f32x2): y_t = x_t @ Wn_{t+1} ----------------
#define BM 128
#define BN 128
#define BK 32
__global__ __launch_bounds__(256, 2) void sgemm_all_kernel(const float* __restrict__ embs) {
    __shared__ __align__(16) float As[BK][BM + 1];
    __shared__ __align__(16) float Bs[BK][BN];
    int t = blockIdx.y;
    const float* A = embs + (size_t)t * NN * DIN;
    const float* B = g_Wn + (t + 1) * DIN * DOUT;
    float* C = g_y + (size_t)t * NN * DOUT;

    int tid = threadIdx.x;           // 256
    int bm = blockIdx.x * BM;
    int tx = tid & 15;               // n: columns tx*2 + 32*j  (j=0..3)
    int ty = tid >> 4;               // m: rows ty*8 .. ty*8+7
    int ar = tid >> 3;               // A-load: row within 32-row pass
    int ac = (tid & 7) * 4;          // A-load: k quad

    ull acc[8][4];
#pragma unroll
    for (int m = 0; m < 8; m++)
#pragma unroll
        for (int j = 0; j < 4; j++) acc[m][j] = 0ull;

    for (int k0 = 0; k0 < DIN; k0 += BK) {
        // A tile 128x32, transposed into As[k][m] (pad +1 -> conflict-free stores)
#pragma unroll
        for (int pass = 0; pass < 4; pass++) {
            int r = pass * 32 + ar;
            int gr = bm + r;
            float4 a4 = make_float4(0.f, 0.f, 0.f, 0.f);
            if (gr < NN) a4 = *(const float4*)&A[(size_t)gr * DIN + k0 + ac];
            As[ac + 0][r] = a4.x;
            As[ac + 1][r] = a4.y;
            As[ac + 2][r] = a4.z;
            As[ac + 3][r] = a4.w;
        }
        // B tile 32x128
#pragma unroll
        for (int pass = 0; pass < 4; pass++) {
            int q = pass * 256 + tid;      // 1024 float4 slots
            int kk = q >> 5;
            int c = (q & 31) * 4;
            *(float4*)&Bs[kk][c] = *(const float4*)&B[(k0 + kk) * BN + c];
        }
        __syncthreads();
#pragma unroll
        for (int kk = 0; kk < BK; kk++) {
            ull b2[4];
#pragma unroll
            for (int j = 0; j < 4; j++)
                b2[j] = *(const ull*)&Bs[kk][tx * 2 + 32 * j];
#pragma unroll
            for (int m = 0; m < 8; m++) {
                float a = As[kk][ty * 8 + m];
                ull a2;
                asm("mov.b64 %0, {%1, %1};" : "=l"(a2) : "f"(a));
#pragma unroll
                for (int j = 0; j < 4; j++)
                    asm("fma.rn.f32x2 %0, %1, %2, %0;"
                        : "+l"(acc[m][j]) : "l"(a2), "l"(b2[j]));
            }
        }
        __syncthreads();
    }
#pragma unroll
    for (int m = 0; m < 8; m++) {
        int gr = bm + ty * 8 + m;
        if (gr < NN) {
#pragma unroll
            for (int j = 0; j < 4; j++)
                *(ull*)&C[(size_t)gr * DOUT + tx * 2 + 32 * j] = acc[m][j];
        }
    }
}

// ---------------- gather + RReLU (batched) ----------------
__global__ void gather_all_kernel(float* __restrict__ out) {
    int t = blockIdx.y;
    int node = blockIdx.x * 8 + (threadIdx.x >> 5);
    if (node >= NN) return;
    int lane = threadIdx.x & 31;
    const int* off = g_off + t * (NN + 1);
    const int* csrc = g_csr_src + (size_t)t * EE;
    const float* cw = g_csr_w + (size_t)t * EE;
    const float* y = g_y + (size_t)t * NN * DOUT;
    int beg = off[node], end = off[node + 1];
    float4 acc = make_float4(0.f, 0.f, 0.f, 0.f);
    int e = beg;
    for (; e + 1 < end; e += 2) {
        int s0 = csrc[e];     float w0 = cw[e];
        int s1 = csrc[e + 1]; float w1 = cw[e + 1];
        float4 v0 = *(const float4*)&y[(size_t)s0 * DOUT + lane * 4];
        float4 v1 = *(const float4*)&y[(size_t)s1 * DOUT + lane * 4];
        acc.x += w0 * v0.x + w1 * v1.x;
        acc.y += w0 * v0.y + w1 * v1.y;
        acc.z += w0 * v0.z + w1 * v1.z;
        acc.w += w0 * v0.w + w1 * v1.w;
    }
    if (e < end) {
        int s0 = csrc[e]; float w0 = cw[e];
        float4 v0 = *(const float4*)&y[(size_t)s0 * DOUT + lane * 4];
        acc.x += w0 * v0.x; acc.y += w0 * v0.y; acc.z += w0 * v0.z; acc.w += w0 * v0.w;
    }
    acc.x = (acc.x >= 0.f) ? acc.x : SLOPE * acc.x;
    acc.y = (acc.y >= 0.f) ? acc.y : SLOPE * acc.y;
    acc.z = (acc.z >= 0.f) ? acc.z : SLOPE * acc.z;
    acc.w = (acc.w >= 0.f) ? acc.w : SLOPE * acc.w;
    *(float4*)&out[((size_t)t * NN + node) * DOUT + lane * 4] = acc;
}

// ---------------- launcher ----------------
extern "C" void kernel_launch(void* const* d_in, const int* in_sizes, int n_in,
                              void* d_out, int out_size) {
    const float* node_embs  = (const float*)d_in[0];   // [T,N,256]
    const int*   edge_index = (const int*)d_in[1];     // [T,2,E]
    const float* edge_w     = (const float*)d_in[2];   // [T,E]
    const float* mask       = (const float*)d_in[3];   // [T,N]
    const float* p          = (const float*)d_in[4];   // [256,1]
    const float* Wz         = (const float*)d_in[5];
    const float* Uz         = (const float*)d_in[6];
    const float* bz         = (const float*)d_in[7];
    const float* Wr         = (const float*)d_in[8];
    const float* Ur         = (const float*)d_in[9];
    const float* br         = (const float*)d_in[10];
    const float* Wh         = (const float*)d_in[11];
    const float* Uh         = (const float*)d_in[12];
    const float* bh         = (const float*)d_in[13];
    const float* W0         = (const float*)d_in[14];
    float* out = (float*)d_out;                        // [T,N,128]

    prep_kernel<<<256, 256>>>(p, Wz, Uz, Wr, Ur, Wh, Uh, W0);

    zero_deg_all_kernel<<<(TT * NN + 255) / 256, 256>>>();
    deg_all_kernel<<<dim3(EE / 256, TT), 256>>>(edge_index);
    scores_all_kernel<<<dim3((NN + 7) / 8, TT), 256>>>(node_embs, p, mask);

    mid_kernel<<<2 * TT, 1024>>>(node_embs);           // scan x4 + topk/xt x4

    fill_all_kernel<<<dim3(EE / 256, TT), 256>>>(edge_index, edge_w);

    for (int t = 0; t < TT; t++)
        gru_kernel<<<DOUT / GCOLS, DIN>>>(t, bz, br, bh);

    sgemm_all_kernel<<<dim3((NN + BM - 1) / BM, TT), 256>>>(node_embs);

    gather_all_kernel<<<dim3((NN + 7) / 8, TT), 256>>>(out);
}